// round 11
// baseline (speedup 1.0000x reference)
#include <cuda_runtime.h>
#include <cstdint>
#include <math.h>

#define HIDDEN 128
#define KQCH   384
#define HH     48
#define WW     64
#define HWP    3072
#define NB     4
#define SCALE  0.05103103630798288f
#define NSPLIT 3

// Scratch (allocation-free rule: __device__ globals)
__device__ float g_val[(size_t)NB*HIDDEN*HWP];
__device__ float g_pval[(size_t)NB*HIDDEN*HWP];
__device__ float g_v2[(size_t)NB*HIDDEN*HWP];
__device__ float g_t1[(size_t)NB*HIDDEN*HWP];
__device__ float g_opart[(size_t)NSPLIT*NB*24*16384];
__device__ float g_lpart[(size_t)NSPLIT*NB*24*128];
__device__ float g_wtV_hi[3][36*4096];
__device__ float g_wtV_lo[3][36*4096];

__device__ __forceinline__ float lrelu(float x) { return x >= 0.f ? x : 0.2f * x; }

// ---------------- PTX helpers -----
__device__ __forceinline__ uint32_t f2tf32(float f) {
    uint32_t u;
    asm("cvt.rna.tf32.f32 %0, %1;" : "=r"(u) : "f"(f));
    return u;
}

#define CP16(dst_u32, src_ptr) \
    asm volatile("cp.async.cg.shared.global [%0], [%1], 16;" \
        :: "r"(dst_u32), "l"(src_ptr))
#define CPCOMMIT() asm volatile("cp.async.commit_group;" ::: "memory")
#define CPWAIT(n)  asm volatile("cp.async.wait_group %0;" :: "n"(n) : "memory")

#define MMA8(c, a, b) \
    asm volatile( \
        "mma.sync.aligned.m16n8k8.row.col.f32.tf32.tf32.f32 " \
        "{%0,%1,%2,%3},{%4,%5,%6,%7},{%8,%9},{%0,%1,%2,%3};" \
        : "+f"((c)[0]), "+f"((c)[1]), "+f"((c)[2]), "+f"((c)[3]) \
        : "r"((a)[0]), "r"((a)[1]), "r"((a)[2]), "r"((a)[3]), \
          "r"((b)[0]), "r"((b)[1]))

// ===========================================================================
// Weight transform: OIHW -> vecA fragment layout + hi/lo split.
// ===========================================================================
__global__ void wt_transpose3(const float* __restrict__ w0,
                              const float* __restrict__ w1,
                              const float* __restrict__ w2,
                              float* __restrict__ dhi, float* __restrict__ dlo)
{
    const int WSZ = 36 * 4096;
    int which = blockIdx.y;
    const float* src = (which == 0) ? w0 : (which == 1) ? w1 : w2;
    int o = blockIdx.x * 256 + threadIdx.x;
    int c = o >> 12;
    int rem = o & 4095;
    int r = rem >> 2, v = rem & 3;
    int mblk = r >> 7, s = (r >> 5) & 3, lane = r & 31;
    int grp = lane >> 2, j0 = lane & 3;
    int k  = c * 32 + s * 8 + j0 + ((v & 2) ? 4 : 0);
    int oc = mblk * 16 + grp + ((v & 1) ? 8 : 0);
    int tap = k >> 7, ic = k & 127;
    float val = src[oc * 1152 + ic * 9 + tap];
    float hi = __uint_as_float(f2tf32(val));
    float lo = __uint_as_float(f2tf32(val - hi));
    dhi[which * WSZ + o] = hi;
    dlo[which * WSZ + o] = lo;
}

// ===========================================================================
// Fused flash attention, split-K x3, vectorized S-phase fragment loads.
//   Q: tuple layout (float4 per a-frag), K: pair layout (float2 per b-frag).
// 256 threads, 8 warps (4 q-rows x 2 cols), 8 key chunks per CTA.
// ===========================================================================
#define SV_STRIDE 132
#define KPR 132                      // K pair-row stride (float2)
// floats: sQ4 2*4096 | sK2 2*4224 | sV 16896 | sP 16896 | sL 256
#define OFF_K2 8192
#define OFF_V  16640
#define OFF_P  (16640 + 16896)
#define OFF_L  (OFF_P + 16896)
#define ATTN_SMEM_FLOATS (OFF_L + 256)
#define ATTN_SMEM_BYTES  (ATTN_SMEM_FLOATS * 4)

__global__ void __launch_bounds__(256, 1) flash_attn(
    const float* __restrict__ qten, const float* __restrict__ kten,
    const float* __restrict__ valten,
    float* __restrict__ opart, float* __restrict__ lpart)
{
    extern __shared__ float sm[];
    float4* sQ4[2] = { (float4*)sm, (float4*)sm + 1024 };
    float4* sK4[2] = { (float4*)(sm + OFF_K2), (float4*)(sm + OFF_K2) + 1056 };
    float*  sV = sm + OFF_V;
    float*  sP = sm + OFF_P;
    float*  sL = sm + OFF_L;

    const uint32_t sVa = (uint32_t)__cvta_generic_to_shared(sV);

    const int tid  = threadIdx.x;
    const int lane = tid & 31;
    const int wid  = tid >> 5;
    const int wr   = wid >> 1;
    const int wc   = wid & 1;
    const int grp  = lane >> 2;
    const int j0   = lane & 3;
    const int z    = blockIdx.y;
    const int spl  = blockIdx.z;
    const int qt   = blockIdx.x;
    const int q0   = qt * 128;

    // Q-stager decomposition
    const int sW  = tid & 3;
    const int jW  = (tid >> 2) & 3;
    const int qqW = (tid >> 4) & 1;
    const int qbW = tid >> 5;
    // K-stager: two assignments a = tid, tid+256

    const float* Qg = qten   + (size_t)z * KQCH  * HWP;
    const float* Kg = kten   + (size_t)z * KQCH  * HWP;
    const float* Vg = valten + (size_t)z * HIDDEN * HWP;

    sL[tid] = 0.f;

    float oacc[2][8][4];
#pragma unroll
    for (int ma = 0; ma < 2; ma++)
#pragma unroll
        for (int na = 0; na < 8; na++)
#pragma unroll
            for (int e = 0; e < 4; e++) oacc[ma][na][e] = 0.f;

    __syncthreads();

    float4 qreg[4], kreg[4];

    const int jbeg = spl * 8, jend = jbeg + 8;
    for (int j = jbeg; j < jend; j++) {
        const int kp0 = j * 128;

        // V tile via cp.async (lands during S phase)
#pragma unroll
        for (int i = 0; i < 16; i++) {
            int idx = tid + i * 256;
            int d = idx >> 5, seg = idx & 31;
            CP16(sVa + (uint32_t)(d * SV_STRIDE + seg * 4) * 4,
                 Vg + (size_t)d * HWP + kp0 + seg * 4);
        }
        CPCOMMIT();

        // --- Q/K staging lambdas ---
        auto ldQK = [&](int cn) {
            {
                int row = cn * 32 + sW * 8 + jW;
                const float* qb = Qg + (size_t)row * HWP + q0 + qbW * 16 + qqW * 4;
                qreg[0] = *(const float4*)(qb);
                qreg[1] = *(const float4*)(qb + 8);
                qreg[2] = *(const float4*)(qb + 4 * HWP);      // row c+4 (fixed)
                qreg[3] = *(const float4*)(qb + 4 * HWP + 8);
            }
#pragma unroll
            for (int r = 0; r < 2; r++) {
                int a = tid + r * 256;
                int cl = a >> 5, kc4 = a & 31;
                int cLow = (cl >> 2) * 8 + (cl & 3);
                const float* kb = Kg + (size_t)(cn * 32 + cLow) * HWP + kp0 + kc4 * 4;
                kreg[2 * r]     = *(const float4*)(kb);
                kreg[2 * r + 1] = *(const float4*)(kb + 4 * HWP);
            }
        };
        auto stQK = [&](int buf) {
            {
                int G = qbW * 4 + sW;
#pragma unroll
                for (int i = 0; i < 4; i++) {
                    float4 t;
                    t.x = (&qreg[0].x)[i]; t.y = (&qreg[1].x)[i];
                    t.z = (&qreg[2].x)[i]; t.w = (&qreg[3].x)[i];
                    sQ4[buf][G * 32 + (qqW * 4 + i) * 4 + jW] = t;
                }
            }
#pragma unroll
            for (int r = 0; r < 2; r++) {
                int a = tid + r * 256;
                int cl = a >> 5, kc4 = a & 31;
                int pr = (cl >> 2) * 4 + (cl & 3);
                float4 u0, u1;
                u0.x = kreg[2 * r].x; u0.y = kreg[2 * r + 1].x;
                u0.z = kreg[2 * r].y; u0.w = kreg[2 * r + 1].y;
                u1.x = kreg[2 * r].z; u1.y = kreg[2 * r + 1].z;
                u1.z = kreg[2 * r].w; u1.w = kreg[2 * r + 1].w;
                sK4[buf][pr * 66 + kc4 * 2]     = u0;
                sK4[buf][pr * 66 + kc4 * 2 + 1] = u1;
            }
        };

        // prologue
        ldQK(0); stQK(0);
        ldQK(1); stQK(1);
        ldQK(2);
        __syncthreads();

        float sacc[2][8][4];
#pragma unroll
        for (int ma = 0; ma < 2; ma++)
#pragma unroll
            for (int na = 0; na < 8; na++)
#pragma unroll
                for (int e = 0; e < 4; e++) sacc[ma][na][e] = 0.f;

        for (int cb = 0; cb < 12; cb++) {
            const int b = cb & 1;
            const float4* qv = sQ4[b];
            const float2* kv = (const float2*)sK4[b];

#pragma unroll
            for (int s = 0; s < 4; s++) {
                uint32_t af[2][4], bf[8][2];
#pragma unroll
                for (int ma = 0; ma < 2; ma++) {
                    float4 a4 = qv[((wr * 2 + ma) * 4 + s) * 32 + lane];
                    af[ma][0] = __float_as_uint(a4.x);
                    af[ma][1] = __float_as_uint(a4.y);
                    af[ma][2] = __float_as_uint(a4.z);
                    af[ma][3] = __float_as_uint(a4.w);
                }
                const int rbase = (s * 4 + j0) * KPR;
#pragma unroll
                for (int na = 0; na < 8; na++) {
                    float2 b2 = kv[rbase + wc * 64 + na * 8 + grp];
                    bf[na][0] = __float_as_uint(b2.x);
                    bf[na][1] = __float_as_uint(b2.y);
                }
#pragma unroll
                for (int ma = 0; ma < 2; ma++)
#pragma unroll
                    for (int na = 0; na < 8; na++)
                        MMA8(sacc[ma][na], af[ma], bf[na]);
            }
            __syncthreads();
            if (cb + 2 < 12) {
                stQK(b);            // regs hold chunk cb+2 -> buffer (cb+2)&1 == b
                if (cb + 3 < 12) ldQK(cb + 3);
            }
        }

        // softmax: P = exp(S*scale), partial row sums
        float rs[4] = {0.f, 0.f, 0.f, 0.f};
#pragma unroll
        for (int ma = 0; ma < 2; ma++)
#pragma unroll
            for (int na = 0; na < 8; na++)
#pragma unroll
                for (int e = 0; e < 4; e++) {
                    float p = __expf(sacc[ma][na][e] * SCALE);
                    sacc[ma][na][e] = p;
                    rs[ma * 2 + (e >> 1)] += p;
                }
#pragma unroll
        for (int i = 0; i < 4; i++) {
            rs[i] += __shfl_xor_sync(0xffffffffu, rs[i], 1);
            rs[i] += __shfl_xor_sync(0xffffffffu, rs[i], 2);
        }
        if (j0 == 0) {
#pragma unroll
            for (int ma = 0; ma < 2; ma++) {
                sL[wc * 128 + wr * 32 + ma * 16 + grp]     += rs[ma * 2];
                sL[wc * 128 + wr * 32 + ma * 16 + grp + 8] += rs[ma * 2 + 1];
            }
        }
#pragma unroll
        for (int ma = 0; ma < 2; ma++) {
            const int row = wr * 32 + ma * 16 + grp;
#pragma unroll
            for (int na = 0; na < 8; na++) {
                const int col = wc * 64 + na * 8 + 2 * j0;
                uint32_t* p0 = (uint32_t*)&sP[row * SV_STRIDE + col];
                p0[0] = f2tf32(sacc[ma][na][0]);
                p0[1] = f2tf32(sacc[ma][na][1]);
                uint32_t* p1 = (uint32_t*)&sP[(row + 8) * SV_STRIDE + col];
                p1[0] = f2tf32(sacc[ma][na][2]);
                p1[1] = f2tf32(sacc[ma][na][3]);
            }
        }
        CPWAIT(0);
        __syncthreads();

        // PV: O += P @ V^T (unchanged)
#pragma unroll
        for (int s = 0; s < 16; s++) {
            const int kr = s * 8 + j0;
            uint32_t af[2][4], bf[8][2];
#pragma unroll
            for (int ma = 0; ma < 2; ma++) {
                const int q = wr * 32 + ma * 16 + grp;
                af[ma][0] = __float_as_uint(sP[q * SV_STRIDE + kr]);
                af[ma][1] = __float_as_uint(sP[(q + 8) * SV_STRIDE + kr]);
                af[ma][2] = __float_as_uint(sP[q * SV_STRIDE + kr + 4]);
                af[ma][3] = __float_as_uint(sP[(q + 8) * SV_STRIDE + kr + 4]);
            }
#pragma unroll
            for (int na = 0; na < 8; na++) {
                const int d = wc * 64 + na * 8 + grp;
                bf[na][0] = __float_as_uint(sV[d * SV_STRIDE + kr]);
                bf[na][1] = __float_as_uint(sV[d * SV_STRIDE + kr + 4]);
            }
#pragma unroll
            for (int ma = 0; ma < 2; ma++)
#pragma unroll
                for (int na = 0; na < 8; na++)
                    MMA8(oacc[ma][na], af[ma], bf[na]);
        }
        __syncthreads();
    }

    // epilogue: stage unnormalized O through sP (transpose), write partial
#pragma unroll
    for (int ma = 0; ma < 2; ma++) {
        const int row = wr * 32 + ma * 16 + grp;
#pragma unroll
        for (int na = 0; na < 8; na++) {
            const int col = wc * 64 + na * 8 + 2 * j0;
            sP[row * SV_STRIDE + col]           = oacc[ma][na][0];
            sP[row * SV_STRIDE + col + 1]       = oacc[ma][na][1];
            sP[(row + 8) * SV_STRIDE + col]     = oacc[ma][na][2];
            sP[(row + 8) * SV_STRIDE + col + 1] = oacc[ma][na][3];
        }
    }
    __syncthreads();
    float* Ob = opart + ((size_t)(spl * NB + z) * 24 + qt) * 16384;
#pragma unroll
    for (int idx = tid; idx < 16384; idx += 256) {
        const int d = idx >> 7, q = idx & 127;
        Ob[idx] = sP[q * SV_STRIDE + d];
    }
    if (tid < 128)
        lpart[((size_t)(spl * NB + z) * 24 + qt) * 128 + tid] = sL[tid] + sL[128 + tid];
}

// ===========================================================================
// Combine: pval[d][hw] = sum_s O_part / sum_s l_part
// ===========================================================================
__global__ void __launch_bounds__(256) attn_combine(
    const float* __restrict__ opart, const float* __restrict__ lpart,
    float* __restrict__ pvalten)
{
    __shared__ float sLinv[128];
    const int qt = blockIdx.x, z = blockIdx.y;
    const int tid = threadIdx.x;
    if (tid < 128) {
        float l = 0.f;
#pragma unroll
        for (int s = 0; s < NSPLIT; s++)
            l += lpart[((size_t)(s * NB + z) * 24 + qt) * 128 + tid];
        sLinv[tid] = 1.f / l;
    }
    __syncthreads();
    float* PO = pvalten + (size_t)z * HIDDEN * HWP;
#pragma unroll
    for (int i = 0; i < 64; i++) {
        int e = tid + i * 256;
        int d = e >> 7, q = e & 127;
        float sum = 0.f;
#pragma unroll
        for (int s = 0; s < NSPLIT; s++)
            sum += opart[((size_t)(s * NB + z) * 24 + qt) * 16384 + e];
        PO[(size_t)d * HWP + qt * 128 + q] = sum * sLinv[q];
    }
}

// ===========================================================================
// 3x3 conv via 3xTF32 mma.sync implicit GEMM (unchanged from R9, passing)
// ===========================================================================
#define BPR 100
#define NTL 96
#define A_CHUNK 4096
#define B_CHUNK (16 * BPR * 2)
#define CONV_SMEM_FLOATS (4 * A_CHUNK + 4 * B_CHUNK)
#define CONV_SMEM_BYTES  (CONV_SMEM_FLOATS * 4)

template<int DIL>
__global__ void __launch_bounds__(256, 1) conv_mma(
    const float* __restrict__ in,
    const float* __restrict__ wtHi, const float* __restrict__ wtLo,
    const float* __restrict__ Res, float* __restrict__ out, int epi)
{
    extern __shared__ float sm[];
    float* sAhi[2] = { sm,               sm + A_CHUNK };
    float* sAlo[2] = { sm + 2 * A_CHUNK, sm + 3 * A_CHUNK };
    float* sBhi[2] = { sm + 4 * A_CHUNK,             sm + 4 * A_CHUNK + B_CHUNK };
    float* sBlo[2] = { sm + 4 * A_CHUNK + 2*B_CHUNK, sm + 4 * A_CHUNK + 3*B_CHUNK };
    uint32_t sAhia[2], sAloa[2];
#pragma unroll
    for (int b = 0; b < 2; b++) {
        sAhia[b] = (uint32_t)__cvta_generic_to_shared(sAhi[b]);
        sAloa[b] = (uint32_t)__cvta_generic_to_shared(sAlo[b]);
    }

    const int tid  = threadIdx.x;
    const int lane = tid & 31;
    const int wid  = tid >> 5;
    const int wr   = wid >> 1;
    const int wc   = wid & 1;
    const int grp  = lane >> 2;
    const int j0   = lane & 3;
    const int z    = blockIdx.y;
    const int n0   = blockIdx.x * NTL;

    const float* inb = in + (size_t)z * HIDDEN * HWP;
    float* outb = out + (size_t)z * HIDDEN * HWP;
    const float* Rb = Res ? Res + (size_t)z * HIDDEN * HWP : nullptr;

    float acc[2][6][4];
#pragma unroll
    for (int ma = 0; ma < 2; ma++)
#pragma unroll
        for (int na = 0; na < 6; na++)
#pragma unroll
            for (int e = 0; e < 4; e++) acc[ma][na][e] = 0.f;

    float breg[12];

    auto loadB = [&](int c) {
        const int tap = c >> 2, ic0 = (c & 3) * 32;
        const int dy = (tap / 3 - 1) * DIL, dx = (tap % 3 - 1) * DIL;
#pragma unroll
        for (int i = 0; i < 12; i++) {
            int idx = i * 256 + tid;
            int row = idx / NTL, col = idx - row * NTL;
            int p = n0 + col;
            int y = p >> 6, x = p & 63;
            int yy = y + dy, xx = x + dx;
            float v = 0.f;
            if ((unsigned)yy < HH && (unsigned)xx < WW)
                v = inb[(size_t)(ic0 + row) * HWP + yy * WW + xx];
            breg[i] = v;
        }
    };
    auto storeB = [&](int buf) {
#pragma unroll
        for (int i = 0; i < 12; i++) {
            int idx = i * 256 + tid;
            int row = idx / NTL, col = idx - row * NTL;
            int fi = ((row >> 3) * 4 + (row & 3)) * (BPR * 2) + col * 2 + ((row & 7) >> 2);
            float v = breg[i];
            float hi = __uint_as_float(f2tf32(v));
            float lo = __uint_as_float(f2tf32(v - hi));
            sBhi[buf][fi] = hi;
            sBlo[buf][fi] = lo;
        }
    };
    auto cpA = [&](int c, int buf) {
        const float* bh = wtHi + (size_t)c * A_CHUNK;
        const float* bl = wtLo + (size_t)c * A_CHUNK;
#pragma unroll
        for (int i = 0; i < 4; i++) {
            int idx = i * 256 + tid;
            CP16(sAhia[buf] + (uint32_t)idx * 16, bh + idx * 4);
            CP16(sAloa[buf] + (uint32_t)idx * 16, bl + idx * 4);
        }
    };

    loadB(0); storeB(0); cpA(0, 0); CPCOMMIT();
    loadB(1); cpA(1, 1); CPCOMMIT();
    CPWAIT(1);
    __syncthreads();
    storeB(1);
    loadB(2);

    for (int c = 0; c < 36; c++) {
        const int b = c & 1;

#pragma unroll
        for (int p = 0; p < 3; p++) {
            const float4* abv = reinterpret_cast<const float4*>((p == 2) ? sAlo[b] : sAhi[b]);
            const float2* bbv = reinterpret_cast<const float2*>((p == 1) ? sBlo[b] : sBhi[b]);
#pragma unroll
            for (int s = 0; s < 4; s++) {
                uint32_t af[2][4], bf[6][2];
#pragma unroll
                for (int ma = 0; ma < 2; ma++) {
                    float4 a4 = abv[((wr * 2 + ma) * 4 + s) * 32 + lane];
                    af[ma][0] = __float_as_uint(a4.x);
                    af[ma][1] = __float_as_uint(a4.y);
                    af[ma][2] = __float_as_uint(a4.z);
                    af[ma][3] = __float_as_uint(a4.w);
                }
#pragma unroll
                for (int na = 0; na < 6; na++) {
                    const int n = wc * 48 + na * 8 + grp;
                    float2 b2 = bbv[(s * 4 + j0) * BPR + n];
                    bf[na][0] = __float_as_uint(b2.x);
                    bf[na][1] = __float_as_uint(b2.y);
                }
#pragma unroll
                for (int ma = 0; ma < 2; ma++)
#pragma unroll
                    for (int na = 0; na < 6; na++)
                        MMA8(acc[ma][na], af[ma], bf[na]);
            }
        }
        __syncthreads();

        if (c + 2 < 36) {
            storeB((c + 2) & 1);
            cpA(c + 2, (c + 2) & 1);
            CPCOMMIT();
            if (c + 3 < 36) loadB(c + 3);
            CPWAIT(1);
        } else {
            CPWAIT(0);
        }
        __syncthreads();
    }

#pragma unroll
    for (int ma = 0; ma < 2; ma++) {
        const int r0 = wr * 32 + ma * 16 + grp;
#pragma unroll
        for (int na = 0; na < 6; na++) {
            const int cc = n0 + wc * 48 + na * 8 + 2 * j0;
#pragma unroll
            for (int h = 0; h < 2; h++) {
                const int r = r0 + h * 8;
#pragma unroll
                for (int e = 0; e < 2; e++) {
                    float vv = acc[ma][na][h * 2 + e];
                    vv = lrelu(vv);
                    if (epi == 2) vv += Rb[(size_t)r * HWP + cc + e];
                    outb[(size_t)r * HWP + cc + e] = vv;
                }
            }
        }
    }
}

// ===========================================================================
// CUDA-core SGEMM for the 1x1 conv (fp32, exact)
// ===========================================================================
__global__ void __launch_bounds__(256) sgemm_1x1(
    const float* __restrict__ A, const float* __restrict__ B,
    float* __restrict__ C)
{
    __shared__ float As[8][128];
    __shared__ float Bs[8][128];

    int z = blockIdx.z;
    B += (long long)z * HIDDEN * HWP;
    C += (long long)z * HIDDEN * HWP;

    int n0 = blockIdx.x * 128;
    int tid = threadIdx.x;
    int tx = tid & 15, ty = tid >> 4;

    float acc[8][8];
#pragma unroll
    for (int i = 0; i < 8; i++)
#pragma unroll
        for (int j2 = 0; j2 < 8; j2++) acc[i][j2] = 0.f;

    for (int k0 = 0; k0 < HIDDEN; k0 += 8) {
        {
            int kk = tid >> 5, c = (tid & 31) * 4;
            float4 bv = *reinterpret_cast<const float4*>(
                &B[(long long)(k0 + kk) * HWP + n0 + c]);
            Bs[kk][c] = bv.x; Bs[kk][c + 1] = bv.y;
            Bs[kk][c + 2] = bv.z; Bs[kk][c + 3] = bv.w;
        }
        {
            int r = tid >> 1, c = (tid & 1) * 4;
            float4 av = *reinterpret_cast<const float4*>(
                &A[(long long)r * HIDDEN + k0 + c]);
            As[c][r] = av.x; As[c + 1][r] = av.y;
            As[c + 2][r] = av.z; As[c + 3][r] = av.w;
        }
        __syncthreads();

#pragma unroll
        for (int kk = 0; kk < 8; kk++) {
            float a[8], b[8];
#pragma unroll
            for (int i = 0; i < 8; i++) a[i] = As[kk][ty * 8 + i];
#pragma unroll
            for (int j2 = 0; j2 < 8; j2++) b[j2] = Bs[kk][tx * 8 + j2];
#pragma unroll
            for (int i = 0; i < 8; i++)
#pragma unroll
                for (int j2 = 0; j2 < 8; j2++)
                    acc[i][j2] = fmaf(a[i], b[j2], acc[i][j2]);
        }
        __syncthreads();
    }

#pragma unroll
    for (int i = 0; i < 8; i++) {
        int gi = ty * 8 + i;
#pragma unroll
        for (int j2 = 0; j2 < 8; j2++)
            C[(long long)gi * HWP + n0 + tx * 8 + j2] = acc[i][j2];
    }
}

// ===========================================================================

extern "C" void kernel_launch(void* const* d_in, const int* in_sizes, int n_in,
                              void* d_out, int out_size)
{
    const float* k_in    = (const float*)d_in[0];
    const float* q_in    = (const float*)d_in[1];
    const float* v_in    = (const float*)d_in[2];
    const float* w_value = (const float*)d_in[3];
    const float* w_out   = (const float*)d_in[4];
    const float* w_ff1   = (const float*)d_in[5];
    const float* w_ff2   = (const float*)d_in[6];
    float* out = (float*)d_out;

    float *val, *pval, *v2, *t1, *wtHi, *wtLo, *opart, *lpart;
    cudaGetSymbolAddress((void**)&val,   g_val);
    cudaGetSymbolAddress((void**)&pval,  g_pval);
    cudaGetSymbolAddress((void**)&v2,    g_v2);
    cudaGetSymbolAddress((void**)&t1,    g_t1);
    cudaGetSymbolAddress((void**)&wtHi,  g_wtV_hi);
    cudaGetSymbolAddress((void**)&wtLo,  g_wtV_lo);
    cudaGetSymbolAddress((void**)&opart, g_opart);
    cudaGetSymbolAddress((void**)&lpart, g_lpart);
    const int WSZ = 36 * 4096;

    static int attr_set = 0;
    if (!attr_set) {
        cudaFuncSetAttribute(flash_attn,
            cudaFuncAttributeMaxDynamicSharedMemorySize, ATTN_SMEM_BYTES);
        cudaFuncSetAttribute(conv_mma<1>,
            cudaFuncAttributeMaxDynamicSharedMemorySize, CONV_SMEM_BYTES);
        cudaFuncSetAttribute(conv_mma<2>,
            cudaFuncAttributeMaxDynamicSharedMemorySize, CONV_SMEM_BYTES);
        attr_set = 1;
    }

    // 0) weight transform -> vecA fragment layout, hi/lo
    wt_transpose3<<<dim3(WSZ / 256, 3), 256>>>(w_out, w_ff1, w_ff2, wtHi, wtLo);

    // 1) val = w_value @ v (1x1 conv, fp32)
    sgemm_1x1<<<dim3(HWP / 128, 1, NB), 256>>>(w_value, v_in, val);

    // 2) split-K flash attention (288 CTAs) + combine -> p_val [d, hw]
    flash_attn<<<dim3(24, NB, NSPLIT), 256, ATTN_SMEM_BYTES>>>(
        q_in, k_in, val, opart, lpart);
    attn_combine<<<dim3(24, NB), 256>>>(opart, lpart, pval);

    // 3) v2 = v + lrelu(conv3x3(p_val, w_out, pad=1))   [3xTF32]
    conv_mma<1><<<dim3(HWP / NTL, NB), 256, CONV_SMEM_BYTES>>>(
        pval, wtHi, wtLo, v_in, v2, 2);

    // 4) t1 = lrelu(conv3x3(v2, w_ff1, pad=2, dil=2))   [3xTF32]
    conv_mma<2><<<dim3(HWP / NTL, NB), 256, CONV_SMEM_BYTES>>>(
        v2, wtHi + WSZ, wtLo + WSZ, nullptr, t1, 1);

    // 5) out = v2 + lrelu(conv3x3(t1, w_ff2, pad=1))    [3xTF32]
    conv_mma<1><<<dim3(HWP / NTL, NB), 256, CONV_SMEM_BYTES>>>(
        t1, wtHi + 2 * WSZ, wtLo + 2 * WSZ, v2, out, 2);
}

// round 12
// speedup vs baseline: 1.2787x; 1.2787x over previous
#include <cuda_runtime.h>
#include <cstdint>
#include <math.h>

#define HIDDEN 128
#define KQCH   384
#define HH     48
#define WW     64
#define HWP    3072
#define NB     4
#define SCALE  0.05103103630798288f
#define NSPLIT 3

// Scratch (allocation-free rule: __device__ globals)
__device__ float g_val[(size_t)NB*HIDDEN*HWP];
__device__ float g_pval[(size_t)NB*HIDDEN*HWP];
__device__ float g_v2[(size_t)NB*HIDDEN*HWP];
__device__ float g_t1[(size_t)NB*HIDDEN*HWP];
__device__ float g_opart[(size_t)NSPLIT*NB*24*16384];
__device__ float g_lpart[(size_t)NSPLIT*NB*24*128];
__device__ float g_wtV_hi[3][36*4096];
__device__ float g_wtV_lo[3][36*4096];

__device__ __forceinline__ float lrelu(float x) { return x >= 0.f ? x : 0.2f * x; }

// ---------------- PTX helpers -----
__device__ __forceinline__ uint32_t f2tf32(float f) {
    uint32_t u;
    asm("cvt.rna.tf32.f32 %0, %1;" : "=r"(u) : "f"(f));
    return u;
}

#define CP16(dst_u32, src_ptr) \
    asm volatile("cp.async.cg.shared.global [%0], [%1], 16;" \
        :: "r"(dst_u32), "l"(src_ptr))
#define CPCOMMIT() asm volatile("cp.async.commit_group;" ::: "memory")
#define CPWAIT(n)  asm volatile("cp.async.wait_group %0;" :: "n"(n) : "memory")

#define MMA8(c, a, b) \
    asm volatile( \
        "mma.sync.aligned.m16n8k8.row.col.f32.tf32.tf32.f32 " \
        "{%0,%1,%2,%3},{%4,%5,%6,%7},{%8,%9},{%0,%1,%2,%3};" \
        : "+f"((c)[0]), "+f"((c)[1]), "+f"((c)[2]), "+f"((c)[3]) \
        : "r"((a)[0]), "r"((a)[1]), "r"((a)[2]), "r"((a)[3]), \
          "r"((b)[0]), "r"((b)[1]))

// ===========================================================================
// Weight transform: OIHW -> vecA fragment layout + hi/lo split.
// ===========================================================================
__global__ void wt_transpose3(const float* __restrict__ w0,
                              const float* __restrict__ w1,
                              const float* __restrict__ w2,
                              float* __restrict__ dhi, float* __restrict__ dlo)
{
    const int WSZ = 36 * 4096;
    int which = blockIdx.y;
    const float* src = (which == 0) ? w0 : (which == 1) ? w1 : w2;
    int o = blockIdx.x * 256 + threadIdx.x;
    int c = o >> 12;
    int rem = o & 4095;
    int r = rem >> 2, v = rem & 3;
    int mblk = r >> 7, s = (r >> 5) & 3, lane = r & 31;
    int grp = lane >> 2, j0 = lane & 3;
    int k  = c * 32 + s * 8 + j0 + ((v & 2) ? 4 : 0);
    int oc = mblk * 16 + grp + ((v & 1) ? 8 : 0);
    int tap = k >> 7, ic = k & 127;
    float val = src[oc * 1152 + ic * 9 + tap];
    float hi = __uint_as_float(f2tf32(val));
    float lo = __uint_as_float(f2tf32(val - hi));
    dhi[which * WSZ + o] = hi;
    dlo[which * WSZ + o] = lo;
}

// ===========================================================================
// Fused flash attention, split-K x3 (R9 version verbatim — cp.async S-phase).
// 256 threads, 8 warps (4 q-rows x 2 cols), 8 key chunks per CTA.
// ===========================================================================
#define SQ_STRIDE 136
#define SV_STRIDE 132
#define ATTN_SMEM_FLOATS (2*32*136 + 2*32*136 + 128*132 + 128*132 + 256)
#define ATTN_SMEM_BYTES  (ATTN_SMEM_FLOATS * 4)

__global__ void __launch_bounds__(256, 1) flash_attn(
    const float* __restrict__ qten, const float* __restrict__ kten,
    const float* __restrict__ valten,
    float* __restrict__ opart, float* __restrict__ lpart)
{
    extern __shared__ float sm[];
    float* sQ = sm;
    float* sK = sQ + 2 * 32 * SQ_STRIDE;
    float* sV = sK + 2 * 32 * SQ_STRIDE;
    float* sP = sV + 128 * SV_STRIDE;
    float* sL = sP + 128 * SV_STRIDE;

    const uint32_t sQa = (uint32_t)__cvta_generic_to_shared(sQ);
    const uint32_t sKa = (uint32_t)__cvta_generic_to_shared(sK);
    const uint32_t sVa = (uint32_t)__cvta_generic_to_shared(sV);

    const int tid  = threadIdx.x;
    const int lane = tid & 31;
    const int wid  = tid >> 5;
    const int wr   = wid >> 1;
    const int wc   = wid & 1;
    const int grp  = lane >> 2;
    const int j0   = lane & 3;
    const int z    = blockIdx.y;
    const int spl  = blockIdx.z;
    const int qt   = blockIdx.x;
    const int q0   = qt * 128;

    const float* Qg = qten   + (size_t)z * KQCH  * HWP;
    const float* Kg = kten   + (size_t)z * KQCH  * HWP;
    const float* Vg = valten + (size_t)z * HIDDEN * HWP;

    sL[tid] = 0.f;

    float oacc[2][8][4];
#pragma unroll
    for (int ma = 0; ma < 2; ma++)
#pragma unroll
        for (int na = 0; na < 8; na++)
#pragma unroll
            for (int e = 0; e < 4; e++) oacc[ma][na][e] = 0.f;

    __syncthreads();

    const int jbeg = spl * 8, jend = jbeg + 8;
    for (int j = jbeg; j < jend; j++) {
        const int kp0 = j * 128;

#pragma unroll
        for (int i = 0; i < 16; i++) {
            int idx = tid + i * 256;
            int d = idx >> 5, seg = idx & 31;
            CP16(sVa + (uint32_t)(d * SV_STRIDE + seg * 4) * 4,
                 Vg + (size_t)d * HWP + kp0 + seg * 4);
        }
        CPCOMMIT();

#pragma unroll
        for (int c = 0; c < 2; c++) {
#pragma unroll
            for (int i = 0; i < 4; i++) {
                int idx = tid + i * 256;
                int cl = idx >> 5, seg = idx & 31;
                uint32_t off = (uint32_t)(c * 32 * SQ_STRIDE + cl * SQ_STRIDE + seg * 4) * 4;
                CP16(sQa + off, Qg + (size_t)(c * 32 + cl) * HWP + q0 + seg * 4);
                CP16(sKa + off, Kg + (size_t)(c * 32 + cl) * HWP + kp0 + seg * 4);
            }
            CPCOMMIT();
        }

        float sacc[2][8][4];
#pragma unroll
        for (int ma = 0; ma < 2; ma++)
#pragma unroll
            for (int na = 0; na < 8; na++)
#pragma unroll
                for (int e = 0; e < 4; e++) sacc[ma][na][e] = 0.f;

        for (int cb = 0; cb < 12; cb++) {
            if (cb < 11) { CPWAIT(1); } else { CPWAIT(0); }
            __syncthreads();

            const int b = cb & 1;
            const float* qb = sQ + b * 32 * SQ_STRIDE;
            const float* kb = sK + b * 32 * SQ_STRIDE;

#pragma unroll
            for (int s = 0; s < 4; s++) {
                const int cr = s * 8 + j0;
                uint32_t af[2][4], bf[8][2];
#pragma unroll
                for (int ma = 0; ma < 2; ma++) {
                    const int q = wr * 32 + ma * 16 + grp;
                    af[ma][0] = __float_as_uint(qb[cr * SQ_STRIDE + q]);
                    af[ma][1] = __float_as_uint(qb[cr * SQ_STRIDE + q + 8]);
                    af[ma][2] = __float_as_uint(qb[(cr + 4) * SQ_STRIDE + q]);
                    af[ma][3] = __float_as_uint(qb[(cr + 4) * SQ_STRIDE + q + 8]);
                }
#pragma unroll
                for (int na = 0; na < 8; na++) {
                    const int kc = wc * 64 + na * 8 + grp;
                    bf[na][0] = __float_as_uint(kb[cr * SQ_STRIDE + kc]);
                    bf[na][1] = __float_as_uint(kb[(cr + 4) * SQ_STRIDE + kc]);
                }
#pragma unroll
                for (int ma = 0; ma < 2; ma++)
#pragma unroll
                    for (int na = 0; na < 8; na++)
                        MMA8(sacc[ma][na], af[ma], bf[na]);
            }
            __syncthreads();

            if (cb + 2 < 12) {
                const int cn = cb + 2;
#pragma unroll
                for (int i = 0; i < 4; i++) {
                    int idx = tid + i * 256;
                    int cl = idx >> 5, seg = idx & 31;
                    uint32_t off = (uint32_t)((cb & 1) * 32 * SQ_STRIDE + cl * SQ_STRIDE + seg * 4) * 4;
                    CP16(sQa + off, Qg + (size_t)(cn * 32 + cl) * HWP + q0 + seg * 4);
                    CP16(sKa + off, Kg + (size_t)(cn * 32 + cl) * HWP + kp0 + seg * 4);
                }
                CPCOMMIT();
            }
        }

        float rs[4] = {0.f, 0.f, 0.f, 0.f};
#pragma unroll
        for (int ma = 0; ma < 2; ma++)
#pragma unroll
            for (int na = 0; na < 8; na++)
#pragma unroll
                for (int e = 0; e < 4; e++) {
                    float p = __expf(sacc[ma][na][e] * SCALE);
                    sacc[ma][na][e] = p;
                    rs[ma * 2 + (e >> 1)] += p;
                }
#pragma unroll
        for (int i = 0; i < 4; i++) {
            rs[i] += __shfl_xor_sync(0xffffffffu, rs[i], 1);
            rs[i] += __shfl_xor_sync(0xffffffffu, rs[i], 2);
        }
        if (j0 == 0) {
#pragma unroll
            for (int ma = 0; ma < 2; ma++) {
                sL[wc * 128 + wr * 32 + ma * 16 + grp]     += rs[ma * 2];
                sL[wc * 128 + wr * 32 + ma * 16 + grp + 8] += rs[ma * 2 + 1];
            }
        }
#pragma unroll
        for (int ma = 0; ma < 2; ma++) {
            const int row = wr * 32 + ma * 16 + grp;
#pragma unroll
            for (int na = 0; na < 8; na++) {
                const int col = wc * 64 + na * 8 + 2 * j0;
                uint32_t* p0 = (uint32_t*)&sP[row * SV_STRIDE + col];
                p0[0] = f2tf32(sacc[ma][na][0]);
                p0[1] = f2tf32(sacc[ma][na][1]);
                uint32_t* p1 = (uint32_t*)&sP[(row + 8) * SV_STRIDE + col];
                p1[0] = f2tf32(sacc[ma][na][2]);
                p1[1] = f2tf32(sacc[ma][na][3]);
            }
        }
        CPWAIT(0);
        __syncthreads();

#pragma unroll
        for (int s = 0; s < 16; s++) {
            const int kr = s * 8 + j0;
            uint32_t af[2][4], bf[8][2];
#pragma unroll
            for (int ma = 0; ma < 2; ma++) {
                const int q = wr * 32 + ma * 16 + grp;
                af[ma][0] = __float_as_uint(sP[q * SV_STRIDE + kr]);
                af[ma][1] = __float_as_uint(sP[(q + 8) * SV_STRIDE + kr]);
                af[ma][2] = __float_as_uint(sP[q * SV_STRIDE + kr + 4]);
                af[ma][3] = __float_as_uint(sP[(q + 8) * SV_STRIDE + kr + 4]);
            }
#pragma unroll
            for (int na = 0; na < 8; na++) {
                const int d = wc * 64 + na * 8 + grp;
                bf[na][0] = __float_as_uint(sV[d * SV_STRIDE + kr]);
                bf[na][1] = __float_as_uint(sV[d * SV_STRIDE + kr + 4]);
            }
#pragma unroll
            for (int ma = 0; ma < 2; ma++)
#pragma unroll
                for (int na = 0; na < 8; na++)
                    MMA8(oacc[ma][na], af[ma], bf[na]);
        }
        __syncthreads();
    }

    // epilogue: stage unnormalized O through sP (transpose), write partial
#pragma unroll
    for (int ma = 0; ma < 2; ma++) {
        const int row = wr * 32 + ma * 16 + grp;
#pragma unroll
        for (int na = 0; na < 8; na++) {
            const int col = wc * 64 + na * 8 + 2 * j0;
            sP[row * SV_STRIDE + col]           = oacc[ma][na][0];
            sP[row * SV_STRIDE + col + 1]       = oacc[ma][na][1];
            sP[(row + 8) * SV_STRIDE + col]     = oacc[ma][na][2];
            sP[(row + 8) * SV_STRIDE + col + 1] = oacc[ma][na][3];
        }
    }
    __syncthreads();
    float* Ob = opart + ((size_t)(spl * NB + z) * 24 + qt) * 16384;
#pragma unroll
    for (int idx = tid; idx < 16384; idx += 256) {
        const int d = idx >> 7, q = idx & 127;
        Ob[idx] = sP[q * SV_STRIDE + d];
    }
    if (tid < 128)
        lpart[((size_t)(spl * NB + z) * 24 + qt) * 128 + tid] = sL[tid] + sL[128 + tid];
}

// ===========================================================================
// Combine: pval[d][hw] = sum_s O_part / sum_s l_part
// ===========================================================================
__global__ void __launch_bounds__(256) attn_combine(
    const float* __restrict__ opart, const float* __restrict__ lpart,
    float* __restrict__ pvalten)
{
    __shared__ float sLinv[128];
    const int qt = blockIdx.x, z = blockIdx.y;
    const int tid = threadIdx.x;
    if (tid < 128) {
        float l = 0.f;
#pragma unroll
        for (int s = 0; s < NSPLIT; s++)
            l += lpart[((size_t)(s * NB + z) * 24 + qt) * 128 + tid];
        sLinv[tid] = 1.f / l;
    }
    __syncthreads();
    float* PO = pvalten + (size_t)z * HIDDEN * HWP;
#pragma unroll
    for (int i = 0; i < 64; i++) {
        int e = tid + i * 256;
        int d = e >> 7, q = e & 127;
        float sum = 0.f;
#pragma unroll
        for (int s = 0; s < NSPLIT; s++)
            sum += opart[((size_t)(s * NB + z) * 24 + qt) * 16384 + e];
        PO[(size_t)d * HWP + qt * 128 + q] = sum * sLinv[q];
    }
}

// ===========================================================================
// 3x3 conv via 3xTF32 mma.sync implicit GEMM (R9 version, passing)
// ===========================================================================
#define BPR 100
#define NTL 96
#define A_CHUNK 4096
#define B_CHUNK (16 * BPR * 2)
#define CONV_SMEM_FLOATS (4 * A_CHUNK + 4 * B_CHUNK)
#define CONV_SMEM_BYTES  (CONV_SMEM_FLOATS * 4)

template<int DIL>
__global__ void __launch_bounds__(256, 1) conv_mma(
    const float* __restrict__ in,
    const float* __restrict__ wtHi, const float* __restrict__ wtLo,
    const float* __restrict__ Res, float* __restrict__ out, int epi)
{
    extern __shared__ float sm[];
    float* sAhi[2] = { sm,               sm + A_CHUNK };
    float* sAlo[2] = { sm + 2 * A_CHUNK, sm + 3 * A_CHUNK };
    float* sBhi[2] = { sm + 4 * A_CHUNK,             sm + 4 * A_CHUNK + B_CHUNK };
    float* sBlo[2] = { sm + 4 * A_CHUNK + 2*B_CHUNK, sm + 4 * A_CHUNK + 3*B_CHUNK };
    uint32_t sAhia[2], sAloa[2];
#pragma unroll
    for (int b = 0; b < 2; b++) {
        sAhia[b] = (uint32_t)__cvta_generic_to_shared(sAhi[b]);
        sAloa[b] = (uint32_t)__cvta_generic_to_shared(sAlo[b]);
    }

    const int tid  = threadIdx.x;
    const int lane = tid & 31;
    const int wid  = tid >> 5;
    const int wr   = wid >> 1;
    const int wc   = wid & 1;
    const int grp  = lane >> 2;
    const int j0   = lane & 3;
    const int z    = blockIdx.y;
    const int n0   = blockIdx.x * NTL;

    const float* inb = in + (size_t)z * HIDDEN * HWP;
    float* outb = out + (size_t)z * HIDDEN * HWP;
    const float* Rb = Res ? Res + (size_t)z * HIDDEN * HWP : nullptr;

    float acc[2][6][4];
#pragma unroll
    for (int ma = 0; ma < 2; ma++)
#pragma unroll
        for (int na = 0; na < 6; na++)
#pragma unroll
            for (int e = 0; e < 4; e++) acc[ma][na][e] = 0.f;

    float breg[12];

    auto loadB = [&](int c) {
        const int tap = c >> 2, ic0 = (c & 3) * 32;
        const int dy = (tap / 3 - 1) * DIL, dx = (tap % 3 - 1) * DIL;
#pragma unroll
        for (int i = 0; i < 12; i++) {
            int idx = i * 256 + tid;
            int row = idx / NTL, col = idx - row * NTL;
            int p = n0 + col;
            int y = p >> 6, x = p & 63;
            int yy = y + dy, xx = x + dx;
            float v = 0.f;
            if ((unsigned)yy < HH && (unsigned)xx < WW)
                v = inb[(size_t)(ic0 + row) * HWP + yy * WW + xx];
            breg[i] = v;
        }
    };
    auto storeB = [&](int buf) {
#pragma unroll
        for (int i = 0; i < 12; i++) {
            int idx = i * 256 + tid;
            int row = idx / NTL, col = idx - row * NTL;
            int fi = ((row >> 3) * 4 + (row & 3)) * (BPR * 2) + col * 2 + ((row & 7) >> 2);
            float v = breg[i];
            float hi = __uint_as_float(f2tf32(v));
            float lo = __uint_as_float(f2tf32(v - hi));
            sBhi[buf][fi] = hi;
            sBlo[buf][fi] = lo;
        }
    };
    auto cpA = [&](int c, int buf) {
        const float* bh = wtHi + (size_t)c * A_CHUNK;
        const float* bl = wtLo + (size_t)c * A_CHUNK;
#pragma unroll
        for (int i = 0; i < 4; i++) {
            int idx = i * 256 + tid;
            CP16(sAhia[buf] + (uint32_t)idx * 16, bh + idx * 4);
            CP16(sAloa[buf] + (uint32_t)idx * 16, bl + idx * 4);
        }
    };

    loadB(0); storeB(0); cpA(0, 0); CPCOMMIT();
    loadB(1); cpA(1, 1); CPCOMMIT();
    CPWAIT(1);
    __syncthreads();
    storeB(1);
    loadB(2);

    for (int c = 0; c < 36; c++) {
        const int b = c & 1;

#pragma unroll
        for (int p = 0; p < 3; p++) {
            const float4* abv = reinterpret_cast<const float4*>((p == 2) ? sAlo[b] : sAhi[b]);
            const float2* bbv = reinterpret_cast<const float2*>((p == 1) ? sBlo[b] : sBhi[b]);
#pragma unroll
            for (int s = 0; s < 4; s++) {
                uint32_t af[2][4], bf[6][2];
#pragma unroll
                for (int ma = 0; ma < 2; ma++) {
                    float4 a4 = abv[((wr * 2 + ma) * 4 + s) * 32 + lane];
                    af[ma][0] = __float_as_uint(a4.x);
                    af[ma][1] = __float_as_uint(a4.y);
                    af[ma][2] = __float_as_uint(a4.z);
                    af[ma][3] = __float_as_uint(a4.w);
                }
#pragma unroll
                for (int na = 0; na < 6; na++) {
                    const int n = wc * 48 + na * 8 + grp;
                    float2 b2 = bbv[(s * 4 + j0) * BPR + n];
                    bf[na][0] = __float_as_uint(b2.x);
                    bf[na][1] = __float_as_uint(b2.y);
                }
#pragma unroll
                for (int ma = 0; ma < 2; ma++)
#pragma unroll
                    for (int na = 0; na < 6; na++)
                        MMA8(acc[ma][na], af[ma], bf[na]);
            }
        }
        __syncthreads();

        if (c + 2 < 36) {
            storeB((c + 2) & 1);
            cpA(c + 2, (c + 2) & 1);
            CPCOMMIT();
            if (c + 3 < 36) loadB(c + 3);
            CPWAIT(1);
        } else {
            CPWAIT(0);
        }
        __syncthreads();
    }

#pragma unroll
    for (int ma = 0; ma < 2; ma++) {
        const int r0 = wr * 32 + ma * 16 + grp;
#pragma unroll
        for (int na = 0; na < 6; na++) {
            const int cc = n0 + wc * 48 + na * 8 + 2 * j0;
#pragma unroll
            for (int h = 0; h < 2; h++) {
                const int r = r0 + h * 8;
#pragma unroll
                for (int e = 0; e < 2; e++) {
                    float vv = acc[ma][na][h * 2 + e];
                    vv = lrelu(vv);
                    if (epi == 2) vv += Rb[(size_t)r * HWP + cc + e];
                    outb[(size_t)r * HWP + cc + e] = vv;
                }
            }
        }
    }
}

// ===========================================================================
// CUDA-core SGEMM for the 1x1 conv (fp32, exact). N-tile 96 -> 128 CTAs.
// ===========================================================================
__global__ void __launch_bounds__(256) sgemm_1x1(
    const float* __restrict__ A, const float* __restrict__ B,
    float* __restrict__ C)
{
    __shared__ float As[8][128];
    __shared__ float Bs[8][96];

    int z = blockIdx.z;
    B += (long long)z * HIDDEN * HWP;
    C += (long long)z * HIDDEN * HWP;

    int n0 = blockIdx.x * 96;
    int tid = threadIdx.x;
    int tx = tid & 15, ty = tid >> 4;

    float acc[8][6];
#pragma unroll
    for (int i = 0; i < 8; i++)
#pragma unroll
        for (int j2 = 0; j2 < 6; j2++) acc[i][j2] = 0.f;

    for (int k0 = 0; k0 < HIDDEN; k0 += 8) {
        {
#pragma unroll
            for (int i = 0; i < 3; i++) {
                int e = tid + i * 256;
                int kk = e / 96, cc = e - kk * 96;
                Bs[kk][cc] = B[(long long)(k0 + kk) * HWP + n0 + cc];
            }
        }
        {
            int r = tid >> 1, c = (tid & 1) * 4;
            float4 av = *reinterpret_cast<const float4*>(
                &A[(long long)r * HIDDEN + k0 + c]);
            As[c][r] = av.x; As[c + 1][r] = av.y;
            As[c + 2][r] = av.z; As[c + 3][r] = av.w;
        }
        __syncthreads();

#pragma unroll
        for (int kk = 0; kk < 8; kk++) {
            float a[8], b[6];
#pragma unroll
            for (int i = 0; i < 8; i++) a[i] = As[kk][ty * 8 + i];
#pragma unroll
            for (int j2 = 0; j2 < 6; j2++) b[j2] = Bs[kk][tx * 6 + j2];
#pragma unroll
            for (int i = 0; i < 8; i++)
#pragma unroll
                for (int j2 = 0; j2 < 6; j2++)
                    acc[i][j2] = fmaf(a[i], b[j2], acc[i][j2]);
        }
        __syncthreads();
    }

#pragma unroll
    for (int i = 0; i < 8; i++) {
        int gi = ty * 8 + i;
#pragma unroll
        for (int j2 = 0; j2 < 6; j2++)
            C[(long long)gi * HWP + n0 + tx * 6 + j2] = acc[i][j2];
    }
}

// ===========================================================================

extern "C" void kernel_launch(void* const* d_in, const int* in_sizes, int n_in,
                              void* d_out, int out_size)
{
    const float* k_in    = (const float*)d_in[0];
    const float* q_in    = (const float*)d_in[1];
    const float* v_in    = (const float*)d_in[2];
    const float* w_value = (const float*)d_in[3];
    const float* w_out   = (const float*)d_in[4];
    const float* w_ff1   = (const float*)d_in[5];
    const float* w_ff2   = (const float*)d_in[6];
    float* out = (float*)d_out;

    float *val, *pval, *v2, *t1, *wtHi, *wtLo, *opart, *lpart;
    cudaGetSymbolAddress((void**)&val,   g_val);
    cudaGetSymbolAddress((void**)&pval,  g_pval);
    cudaGetSymbolAddress((void**)&v2,    g_v2);
    cudaGetSymbolAddress((void**)&t1,    g_t1);
    cudaGetSymbolAddress((void**)&wtHi,  g_wtV_hi);
    cudaGetSymbolAddress((void**)&wtLo,  g_wtV_lo);
    cudaGetSymbolAddress((void**)&opart, g_opart);
    cudaGetSymbolAddress((void**)&lpart, g_lpart);
    const int WSZ = 36 * 4096;

    static int attr_set = 0;
    if (!attr_set) {
        cudaFuncSetAttribute(flash_attn,
            cudaFuncAttributeMaxDynamicSharedMemorySize, ATTN_SMEM_BYTES);
        cudaFuncSetAttribute(conv_mma<1>,
            cudaFuncAttributeMaxDynamicSharedMemorySize, CONV_SMEM_BYTES);
        cudaFuncSetAttribute(conv_mma<2>,
            cudaFuncAttributeMaxDynamicSharedMemorySize, CONV_SMEM_BYTES);
        attr_set = 1;
    }

    // 0) weight transform -> vecA fragment layout, hi/lo
    wt_transpose3<<<dim3(WSZ / 256, 3), 256>>>(w_out, w_ff1, w_ff2, wtHi, wtLo);

    // 1) val = w_value @ v (1x1 conv, fp32), 128 CTAs single wave
    sgemm_1x1<<<dim3(HWP / 96, 1, NB), 256>>>(w_value, v_in, val);

    // 2) split-K flash attention (288 CTAs) + combine -> p_val [d, hw]
    flash_attn<<<dim3(24, NB, NSPLIT), 256, ATTN_SMEM_BYTES>>>(
        q_in, k_in, val, opart, lpart);
    attn_combine<<<dim3(24, NB), 256>>>(opart, lpart, pval);

    // 3) v2 = v + lrelu(conv3x3(p_val, w_out, pad=1))   [3xTF32]
    conv_mma<1><<<dim3(HWP / NTL, NB), 256, CONV_SMEM_BYTES>>>(
        pval, wtHi, wtLo, v_in, v2, 2);

    // 4) t1 = lrelu(conv3x3(v2, w_ff1, pad=2, dil=2))   [3xTF32]
    conv_mma<2><<<dim3(HWP / NTL, NB), 256, CONV_SMEM_BYTES>>>(
        v2, wtHi + WSZ, wtLo + WSZ, nullptr, t1, 1);

    // 5) out = v2 + lrelu(conv3x3(t1, w_ff2, pad=1))    [3xTF32]
    conv_mma<1><<<dim3(HWP / NTL, NB), 256, CONV_SMEM_BYTES>>>(
        t1, wtHi + 2 * WSZ, wtLo + 2 * WSZ, v2, out, 2);
}

// round 13
// speedup vs baseline: 1.2888x; 1.0079x over previous
#include <cuda_runtime.h>
#include <cstdint>
#include <math.h>

#define HIDDEN 128
#define KQCH   384
#define HH     48
#define WW     64
#define HWP    3072
#define NB     4
#define SCALE  0.05103103630798288f
#define NSPLIT 3

// Scratch (allocation-free rule: __device__ globals)
__device__ float g_val[(size_t)NB*HIDDEN*HWP];     // k-columns PERMUTED (pi)
__device__ float g_pval[(size_t)NB*HIDDEN*HWP];
__device__ float g_v2[(size_t)NB*HIDDEN*HWP];
__device__ float g_t1[(size_t)NB*HIDDEN*HWP];
__device__ float g_opart[(size_t)NSPLIT*NB*24*16384];
__device__ float g_lpart[(size_t)NSPLIT*NB*24*128];
__device__ float g_wtV_hi[3][36*4096];
__device__ float g_wtV_lo[3][36*4096];

__device__ __forceinline__ float lrelu(float x) { return x >= 0.f ? x : 0.2f * x; }

// ---------------- PTX helpers -----
__device__ __forceinline__ uint32_t f2tf32(float f) {
    uint32_t u;
    asm("cvt.rna.tf32.f32 %0, %1;" : "=r"(u) : "f"(f));
    return u;
}

#define CP16(dst_u32, src_ptr) \
    asm volatile("cp.async.cg.shared.global [%0], [%1], 16;" \
        :: "r"(dst_u32), "l"(src_ptr))
#define CPCOMMIT() asm volatile("cp.async.commit_group;" ::: "memory")
#define CPWAIT(n)  asm volatile("cp.async.wait_group %0;" :: "n"(n) : "memory")

#define MMA8(c, a, b) \
    asm volatile( \
        "mma.sync.aligned.m16n8k8.row.col.f32.tf32.tf32.f32 " \
        "{%0,%1,%2,%3},{%4,%5,%6,%7},{%8,%9},{%0,%1,%2,%3};" \
        : "+f"((c)[0]), "+f"((c)[1]), "+f"((c)[2]), "+f"((c)[3]) \
        : "r"((a)[0]), "r"((a)[1]), "r"((a)[2]), "r"((a)[3]), \
          "r"((b)[0]), "r"((b)[1]))

// ===========================================================================
// Weight transform: OIHW -> vecA fragment layout + hi/lo split.
// ===========================================================================
__global__ void wt_transpose3(const float* __restrict__ w0,
                              const float* __restrict__ w1,
                              const float* __restrict__ w2,
                              float* __restrict__ dhi, float* __restrict__ dlo)
{
    const int WSZ = 36 * 4096;
    int which = blockIdx.y;
    const float* src = (which == 0) ? w0 : (which == 1) ? w1 : w2;
    int o = blockIdx.x * 256 + threadIdx.x;
    int c = o >> 12;
    int rem = o & 4095;
    int r = rem >> 2, v = rem & 3;
    int mblk = r >> 7, s = (r >> 5) & 3, lane = r & 31;
    int grp = lane >> 2, j0 = lane & 3;
    int k  = c * 32 + s * 8 + j0 + ((v & 2) ? 4 : 0);
    int oc = mblk * 16 + grp + ((v & 1) ? 8 : 0);
    int tap = k >> 7, ic = k & 127;
    float val = src[oc * 1152 + ic * 9 + tap];
    float hi = __uint_as_float(f2tf32(val));
    float lo = __uint_as_float(f2tf32(val - hi));
    dhi[which * WSZ + o] = hi;
    dlo[which * WSZ + o] = lo;
}

// ===========================================================================
// Fused flash attention, split-K x3, pi-permuted V/P for LDS.64 PV loads.
// 256 threads, 8 warps (4 q-rows x 2 cols), 8 key chunks per CTA.
// ===========================================================================
#define SQ_STRIDE 136
#define SPV 136                      // sV / sP float stride (conflict-free f2)
// floats: sQ 2*32*136 | sK 2*32*136 | sV 128*136 | sP 128*136 | sL 256
#define ATTN_SMEM_FLOATS (2*32*136 + 2*32*136 + 128*SPV + 128*SPV + 256)
#define ATTN_SMEM_BYTES  (ATTN_SMEM_FLOATS * 4)

__global__ void __launch_bounds__(256, 1) flash_attn(
    const float* __restrict__ qten, const float* __restrict__ kten,
    const float* __restrict__ valten,
    float* __restrict__ opart, float* __restrict__ lpart)
{
    extern __shared__ float sm[];
    float* sQ = sm;
    float* sK = sQ + 2 * 32 * SQ_STRIDE;
    float* sV = sK + 2 * 32 * SQ_STRIDE;
    float* sP = sV + 128 * SPV;
    float* sL = sP + 128 * SPV;

    const uint32_t sQa = (uint32_t)__cvta_generic_to_shared(sQ);
    const uint32_t sKa = (uint32_t)__cvta_generic_to_shared(sK);
    const uint32_t sVa = (uint32_t)__cvta_generic_to_shared(sV);

    const int tid  = threadIdx.x;
    const int lane = tid & 31;
    const int wid  = tid >> 5;
    const int wr   = wid >> 1;
    const int wc   = wid & 1;
    const int grp  = lane >> 2;
    const int j0   = lane & 3;
    const int z    = blockIdx.y;
    const int spl  = blockIdx.z;
    const int qt   = blockIdx.x;
    const int q0   = qt * 128;

    const float* Qg = qten   + (size_t)z * KQCH  * HWP;
    const float* Kg = kten   + (size_t)z * KQCH  * HWP;
    const float* Vg = valten + (size_t)z * HIDDEN * HWP;

    sL[tid] = 0.f;

    float oacc[2][8][4];
#pragma unroll
    for (int ma = 0; ma < 2; ma++)
#pragma unroll
        for (int na = 0; na < 8; na++)
#pragma unroll
            for (int e = 0; e < 4; e++) oacc[ma][na][e] = 0.f;

    __syncthreads();

    // P store position within 8-col group under pi: cols (2j0, 2j0+1) -> (p, p+2)
    const int ppos = (j0 < 2) ? 4 * j0 : 4 * j0 - 7;

    const int jbeg = spl * 8, jend = jbeg + 8;
    for (int j = jbeg; j < jend; j++) {
        const int kp0 = j * 128;

        // V tile (pi-permuted source) via cp.async, lands during S phase
#pragma unroll
        for (int i = 0; i < 16; i++) {
            int idx = tid + i * 256;
            int d = idx >> 5, seg = idx & 31;
            CP16(sVa + (uint32_t)(d * SPV + seg * 4) * 4,
                 Vg + (size_t)d * HWP + kp0 + seg * 4);
        }
        CPCOMMIT();

#pragma unroll
        for (int c = 0; c < 2; c++) {
#pragma unroll
            for (int i = 0; i < 4; i++) {
                int idx = tid + i * 256;
                int cl = idx >> 5, seg = idx & 31;
                uint32_t off = (uint32_t)(c * 32 * SQ_STRIDE + cl * SQ_STRIDE + seg * 4) * 4;
                CP16(sQa + off, Qg + (size_t)(c * 32 + cl) * HWP + q0 + seg * 4);
                CP16(sKa + off, Kg + (size_t)(c * 32 + cl) * HWP + kp0 + seg * 4);
            }
            CPCOMMIT();
        }

        float sacc[2][8][4];
#pragma unroll
        for (int ma = 0; ma < 2; ma++)
#pragma unroll
            for (int na = 0; na < 8; na++)
#pragma unroll
                for (int e = 0; e < 4; e++) sacc[ma][na][e] = 0.f;

        for (int cb = 0; cb < 12; cb++) {
            if (cb < 11) { CPWAIT(1); } else { CPWAIT(0); }
            __syncthreads();

            const int b = cb & 1;
            const float* qb = sQ + b * 32 * SQ_STRIDE;
            const float* kb = sK + b * 32 * SQ_STRIDE;

#pragma unroll
            for (int s = 0; s < 4; s++) {
                const int cr = s * 8 + j0;
                uint32_t af[2][4], bf[8][2];
#pragma unroll
                for (int ma = 0; ma < 2; ma++) {
                    const int q = wr * 32 + ma * 16 + grp;
                    af[ma][0] = __float_as_uint(qb[cr * SQ_STRIDE + q]);
                    af[ma][1] = __float_as_uint(qb[cr * SQ_STRIDE + q + 8]);
                    af[ma][2] = __float_as_uint(qb[(cr + 4) * SQ_STRIDE + q]);
                    af[ma][3] = __float_as_uint(qb[(cr + 4) * SQ_STRIDE + q + 8]);
                }
#pragma unroll
                for (int na = 0; na < 8; na++) {
                    const int kc = wc * 64 + na * 8 + grp;
                    bf[na][0] = __float_as_uint(kb[cr * SQ_STRIDE + kc]);
                    bf[na][1] = __float_as_uint(kb[(cr + 4) * SQ_STRIDE + kc]);
                }
#pragma unroll
                for (int ma = 0; ma < 2; ma++)
#pragma unroll
                    for (int na = 0; na < 8; na++)
                        MMA8(sacc[ma][na], af[ma], bf[na]);
            }
            __syncthreads();

            if (cb + 2 < 12) {
                const int cn = cb + 2;
#pragma unroll
                for (int i = 0; i < 4; i++) {
                    int idx = tid + i * 256;
                    int cl = idx >> 5, seg = idx & 31;
                    uint32_t off = (uint32_t)((cb & 1) * 32 * SQ_STRIDE + cl * SQ_STRIDE + seg * 4) * 4;
                    CP16(sQa + off, Qg + (size_t)(cn * 32 + cl) * HWP + q0 + seg * 4);
                    CP16(sKa + off, Kg + (size_t)(cn * 32 + cl) * HWP + kp0 + seg * 4);
                }
                CPCOMMIT();
            }
        }

        float rs[4] = {0.f, 0.f, 0.f, 0.f};
#pragma unroll
        for (int ma = 0; ma < 2; ma++)
#pragma unroll
            for (int na = 0; na < 8; na++)
#pragma unroll
                for (int e = 0; e < 4; e++) {
                    float p = __expf(sacc[ma][na][e] * SCALE);
                    sacc[ma][na][e] = p;
                    rs[ma * 2 + (e >> 1)] += p;
                }
#pragma unroll
        for (int i = 0; i < 4; i++) {
            rs[i] += __shfl_xor_sync(0xffffffffu, rs[i], 1);
            rs[i] += __shfl_xor_sync(0xffffffffu, rs[i], 2);
        }
        if (j0 == 0) {
#pragma unroll
            for (int ma = 0; ma < 2; ma++) {
                sL[wc * 128 + wr * 32 + ma * 16 + grp]     += rs[ma * 2];
                sL[wc * 128 + wr * 32 + ma * 16 + grp + 8] += rs[ma * 2 + 1];
            }
        }
        // store P at pi-permuted column positions
#pragma unroll
        for (int ma = 0; ma < 2; ma++) {
            const int row = wr * 32 + ma * 16 + grp;
#pragma unroll
            for (int na = 0; na < 8; na++) {
                const int gb = (wc * 8 + na) * 8 + ppos;
                uint32_t* p0 = (uint32_t*)&sP[row * SPV + gb];
                p0[0] = f2tf32(sacc[ma][na][0]);
                p0[2] = f2tf32(sacc[ma][na][1]);
                uint32_t* p1 = (uint32_t*)&sP[(row + 8) * SPV + gb];
                p1[0] = f2tf32(sacc[ma][na][2]);
                p1[2] = f2tf32(sacc[ma][na][3]);
            }
        }
        CPWAIT(0);
        __syncthreads();

        // PV: O += P @ V^T, LDS.64 fragment loads (pi-paired columns)
        const float2* pv2 = (const float2*)sP;   // stride 68 float2
        const float2* vv2 = (const float2*)sV;
#pragma unroll
        for (int s = 0; s < 16; s++) {
            uint32_t af[2][4], bf[8][2];
#pragma unroll
            for (int ma = 0; ma < 2; ma++) {
                const int q = wr * 32 + ma * 16 + grp;
                float2 a0 = pv2[q * 68 + s * 4 + j0];
                float2 a1 = pv2[(q + 8) * 68 + s * 4 + j0];
                af[ma][0] = __float_as_uint(a0.x);
                af[ma][1] = __float_as_uint(a1.x);
                af[ma][2] = __float_as_uint(a0.y);
                af[ma][3] = __float_as_uint(a1.y);
            }
#pragma unroll
            for (int na = 0; na < 8; na++) {
                const int d = wc * 64 + na * 8 + grp;
                float2 b2 = vv2[d * 68 + s * 4 + j0];
                bf[na][0] = __float_as_uint(b2.x);
                bf[na][1] = __float_as_uint(b2.y);
            }
#pragma unroll
            for (int ma = 0; ma < 2; ma++)
#pragma unroll
                for (int na = 0; na < 8; na++)
                    MMA8(oacc[ma][na], af[ma], bf[na]);
        }
        __syncthreads();
    }

    // epilogue: stage unnormalized O through sP (plain layout), write partial
#pragma unroll
    for (int ma = 0; ma < 2; ma++) {
        const int row = wr * 32 + ma * 16 + grp;
#pragma unroll
        for (int na = 0; na < 8; na++) {
            const int col = wc * 64 + na * 8 + 2 * j0;
            sP[row * SPV + col]           = oacc[ma][na][0];
            sP[row * SPV + col + 1]       = oacc[ma][na][1];
            sP[(row + 8) * SPV + col]     = oacc[ma][na][2];
            sP[(row + 8) * SPV + col + 1] = oacc[ma][na][3];
        }
    }
    __syncthreads();
    float* Ob = opart + ((size_t)(spl * NB + z) * 24 + qt) * 16384;
#pragma unroll
    for (int idx = tid; idx < 16384; idx += 256) {
        const int d = idx >> 7, q = idx & 127;
        Ob[idx] = sP[q * SPV + d];
    }
    if (tid < 128)
        lpart[((size_t)(spl * NB + z) * 24 + qt) * 128 + tid] = sL[tid] + sL[128 + tid];
}

// ===========================================================================
// Combine: pval[d][hw] = sum_s O_part / sum_s l_part
// ===========================================================================
__global__ void __launch_bounds__(256) attn_combine(
    const float* __restrict__ opart, const float* __restrict__ lpart,
    float* __restrict__ pvalten)
{
    __shared__ float sLinv[128];
    const int qt = blockIdx.x, z = blockIdx.y;
    const int tid = threadIdx.x;
    if (tid < 128) {
        float l = 0.f;
#pragma unroll
        for (int s = 0; s < NSPLIT; s++)
            l += lpart[((size_t)(s * NB + z) * 24 + qt) * 128 + tid];
        sLinv[tid] = 1.f / l;
    }
    __syncthreads();
    float* PO = pvalten + (size_t)z * HIDDEN * HWP;
#pragma unroll
    for (int i = 0; i < 64; i++) {
        int e = tid + i * 256;
        int d = e >> 7, q = e & 127;
        float sum = 0.f;
#pragma unroll
        for (int s = 0; s < NSPLIT; s++)
            sum += opart[((size_t)(s * NB + z) * 24 + qt) * 16384 + e];
        PO[(size_t)d * HWP + qt * 128 + q] = sum * sLinv[q];
    }
}

// ===========================================================================
// 3x3 conv via 3xTF32 mma.sync implicit GEMM (R9 version, passing)
// ===========================================================================
#define BPR 100
#define NTL 96
#define A_CHUNK 4096
#define B_CHUNK (16 * BPR * 2)
#define CONV_SMEM_FLOATS (4 * A_CHUNK + 4 * B_CHUNK)
#define CONV_SMEM_BYTES  (CONV_SMEM_FLOATS * 4)

template<int DIL>
__global__ void __launch_bounds__(256, 1) conv_mma(
    const float* __restrict__ in,
    const float* __restrict__ wtHi, const float* __restrict__ wtLo,
    const float* __restrict__ Res, float* __restrict__ out, int epi)
{
    extern __shared__ float sm[];
    float* sAhi[2] = { sm,               sm + A_CHUNK };
    float* sAlo[2] = { sm + 2 * A_CHUNK, sm + 3 * A_CHUNK };
    float* sBhi[2] = { sm + 4 * A_CHUNK,             sm + 4 * A_CHUNK + B_CHUNK };
    float* sBlo[2] = { sm + 4 * A_CHUNK + 2*B_CHUNK, sm + 4 * A_CHUNK + 3*B_CHUNK };
    uint32_t sAhia[2], sAloa[2];
#pragma unroll
    for (int b = 0; b < 2; b++) {
        sAhia[b] = (uint32_t)__cvta_generic_to_shared(sAhi[b]);
        sAloa[b] = (uint32_t)__cvta_generic_to_shared(sAlo[b]);
    }

    const int tid  = threadIdx.x;
    const int lane = tid & 31;
    const int wid  = tid >> 5;
    const int wr   = wid >> 1;
    const int wc   = wid & 1;
    const int grp  = lane >> 2;
    const int j0   = lane & 3;
    const int z    = blockIdx.y;
    const int n0   = blockIdx.x * NTL;

    const float* inb = in + (size_t)z * HIDDEN * HWP;
    float* outb = out + (size_t)z * HIDDEN * HWP;
    const float* Rb = Res ? Res + (size_t)z * HIDDEN * HWP : nullptr;

    float acc[2][6][4];
#pragma unroll
    for (int ma = 0; ma < 2; ma++)
#pragma unroll
        for (int na = 0; na < 6; na++)
#pragma unroll
            for (int e = 0; e < 4; e++) acc[ma][na][e] = 0.f;

    float breg[12];

    auto loadB = [&](int c) {
        const int tap = c >> 2, ic0 = (c & 3) * 32;
        const int dy = (tap / 3 - 1) * DIL, dx = (tap % 3 - 1) * DIL;
#pragma unroll
        for (int i = 0; i < 12; i++) {
            int idx = i * 256 + tid;
            int row = idx / NTL, col = idx - row * NTL;
            int p = n0 + col;
            int y = p >> 6, x = p & 63;
            int yy = y + dy, xx = x + dx;
            float v = 0.f;
            if ((unsigned)yy < HH && (unsigned)xx < WW)
                v = inb[(size_t)(ic0 + row) * HWP + yy * WW + xx];
            breg[i] = v;
        }
    };
    auto storeB = [&](int buf) {
#pragma unroll
        for (int i = 0; i < 12; i++) {
            int idx = i * 256 + tid;
            int row = idx / NTL, col = idx - row * NTL;
            int fi = ((row >> 3) * 4 + (row & 3)) * (BPR * 2) + col * 2 + ((row & 7) >> 2);
            float v = breg[i];
            float hi = __uint_as_float(f2tf32(v));
            float lo = __uint_as_float(f2tf32(v - hi));
            sBhi[buf][fi] = hi;
            sBlo[buf][fi] = lo;
        }
    };
    auto cpA = [&](int c, int buf) {
        const float* bh = wtHi + (size_t)c * A_CHUNK;
        const float* bl = wtLo + (size_t)c * A_CHUNK;
#pragma unroll
        for (int i = 0; i < 4; i++) {
            int idx = i * 256 + tid;
            CP16(sAhia[buf] + (uint32_t)idx * 16, bh + idx * 4);
            CP16(sAloa[buf] + (uint32_t)idx * 16, bl + idx * 4);
        }
    };

    loadB(0); storeB(0); cpA(0, 0); CPCOMMIT();
    loadB(1); cpA(1, 1); CPCOMMIT();
    CPWAIT(1);
    __syncthreads();
    storeB(1);
    loadB(2);

    for (int c = 0; c < 36; c++) {
        const int b = c & 1;

#pragma unroll
        for (int p = 0; p < 3; p++) {
            const float4* abv = reinterpret_cast<const float4*>((p == 2) ? sAlo[b] : sAhi[b]);
            const float2* bbv = reinterpret_cast<const float2*>((p == 1) ? sBlo[b] : sBhi[b]);
#pragma unroll
            for (int s = 0; s < 4; s++) {
                uint32_t af[2][4], bf[6][2];
#pragma unroll
                for (int ma = 0; ma < 2; ma++) {
                    float4 a4 = abv[((wr * 2 + ma) * 4 + s) * 32 + lane];
                    af[ma][0] = __float_as_uint(a4.x);
                    af[ma][1] = __float_as_uint(a4.y);
                    af[ma][2] = __float_as_uint(a4.z);
                    af[ma][3] = __float_as_uint(a4.w);
                }
#pragma unroll
                for (int na = 0; na < 6; na++) {
                    const int n = wc * 48 + na * 8 + grp;
                    float2 b2 = bbv[(s * 4 + j0) * BPR + n];
                    bf[na][0] = __float_as_uint(b2.x);
                    bf[na][1] = __float_as_uint(b2.y);
                }
#pragma unroll
                for (int ma = 0; ma < 2; ma++)
#pragma unroll
                    for (int na = 0; na < 6; na++)
                        MMA8(acc[ma][na], af[ma], bf[na]);
            }
        }
        __syncthreads();

        if (c + 2 < 36) {
            storeB((c + 2) & 1);
            cpA(c + 2, (c + 2) & 1);
            CPCOMMIT();
            if (c + 3 < 36) loadB(c + 3);
            CPWAIT(1);
        } else {
            CPWAIT(0);
        }
        __syncthreads();
    }

#pragma unroll
    for (int ma = 0; ma < 2; ma++) {
        const int r0 = wr * 32 + ma * 16 + grp;
#pragma unroll
        for (int na = 0; na < 6; na++) {
            const int cc = n0 + wc * 48 + na * 8 + 2 * j0;
#pragma unroll
            for (int h = 0; h < 2; h++) {
                const int r = r0 + h * 8;
#pragma unroll
                for (int e = 0; e < 2; e++) {
                    float vv = acc[ma][na][h * 2 + e];
                    vv = lrelu(vv);
                    if (epi == 2) vv += Rb[(size_t)r * HWP + cc + e];
                    outb[(size_t)r * HWP + cc + e] = vv;
                }
            }
        }
    }
}

// ===========================================================================
// CUDA-core SGEMM for the 1x1 conv (fp32, exact), N-tile 96, 128 CTAs.
// Output k-columns pi-permuted within each 8-group (consumed only by flash V).
// ===========================================================================
__global__ void __launch_bounds__(256) sgemm_1x1(
    const float* __restrict__ A, const float* __restrict__ B,
    float* __restrict__ C)
{
    __shared__ float As[8][128];
    __shared__ float Bs[8][96];

    int z = blockIdx.z;
    B += (long long)z * HIDDEN * HWP;
    C += (long long)z * HIDDEN * HWP;

    int n0 = blockIdx.x * 96;
    int tid = threadIdx.x;
    int tx = tid & 15, ty = tid >> 4;

    float acc[8][6];
#pragma unroll
    for (int i = 0; i < 8; i++)
#pragma unroll
        for (int j2 = 0; j2 < 6; j2++) acc[i][j2] = 0.f;

    for (int k0 = 0; k0 < HIDDEN; k0 += 8) {
        {
#pragma unroll
            for (int i = 0; i < 3; i++) {
                int e = tid + i * 256;
                int kk = e / 96, cc = e - kk * 96;
                Bs[kk][cc] = B[(long long)(k0 + kk) * HWP + n0 + cc];
            }
        }
        {
            int r = tid >> 1, c = (tid & 1) * 4;
            float4 av = *reinterpret_cast<const float4*>(
                &A[(long long)r * HIDDEN + k0 + c]);
            As[c][r] = av.x; As[c + 1][r] = av.y;
            As[c + 2][r] = av.z; As[c + 3][r] = av.w;
        }
        __syncthreads();

#pragma unroll
        for (int kk = 0; kk < 8; kk++) {
            float a[8], b[6];
#pragma unroll
            for (int i = 0; i < 8; i++) a[i] = As[kk][ty * 8 + i];
#pragma unroll
            for (int j2 = 0; j2 < 6; j2++) b[j2] = Bs[kk][tx * 6 + j2];
#pragma unroll
            for (int i = 0; i < 8; i++)
#pragma unroll
                for (int j2 = 0; j2 < 6; j2++)
                    acc[i][j2] = fmaf(a[i], b[j2], acc[i][j2]);
        }
        __syncthreads();
    }

#pragma unroll
    for (int i = 0; i < 8; i++) {
        int gi = ty * 8 + i;
#pragma unroll
        for (int j2 = 0; j2 < 6; j2++) {
            int n = n0 + tx * 6 + j2;
            int l = n & 7;
            int pos = (l < 4) ? 2 * l : 2 * (l - 4) + 1;   // pi permutation
            C[(long long)gi * HWP + (n & ~7) + pos] = acc[i][j2];
        }
    }
}

// ===========================================================================

extern "C" void kernel_launch(void* const* d_in, const int* in_sizes, int n_in,
                              void* d_out, int out_size)
{
    const float* k_in    = (const float*)d_in[0];
    const float* q_in    = (const float*)d_in[1];
    const float* v_in    = (const float*)d_in[2];
    const float* w_value = (const float*)d_in[3];
    const float* w_out   = (const float*)d_in[4];
    const float* w_ff1   = (const float*)d_in[5];
    const float* w_ff2   = (const float*)d_in[6];
    float* out = (float*)d_out;

    float *val, *pval, *v2, *t1, *wtHi, *wtLo, *opart, *lpart;
    cudaGetSymbolAddress((void**)&val,   g_val);
    cudaGetSymbolAddress((void**)&pval,  g_pval);
    cudaGetSymbolAddress((void**)&v2,    g_v2);
    cudaGetSymbolAddress((void**)&t1,    g_t1);
    cudaGetSymbolAddress((void**)&wtHi,  g_wtV_hi);
    cudaGetSymbolAddress((void**)&wtLo,  g_wtV_lo);
    cudaGetSymbolAddress((void**)&opart, g_opart);
    cudaGetSymbolAddress((void**)&lpart, g_lpart);
    const int WSZ = 36 * 4096;

    static int attr_set = 0;
    if (!attr_set) {
        cudaFuncSetAttribute(flash_attn,
            cudaFuncAttributeMaxDynamicSharedMemorySize, ATTN_SMEM_BYTES);
        cudaFuncSetAttribute(conv_mma<1>,
            cudaFuncAttributeMaxDynamicSharedMemorySize, CONV_SMEM_BYTES);
        cudaFuncSetAttribute(conv_mma<2>,
            cudaFuncAttributeMaxDynamicSharedMemorySize, CONV_SMEM_BYTES);
        attr_set = 1;
    }

    // 0) weight transform -> vecA fragment layout, hi/lo
    wt_transpose3<<<dim3(WSZ / 256, 3), 256>>>(w_out, w_ff1, w_ff2, wtHi, wtLo);

    // 1) val = w_value @ v (1x1 conv, fp32, pi-permuted k-columns)
    sgemm_1x1<<<dim3(HWP / 96, 1, NB), 256>>>(w_value, v_in, val);

    // 2) split-K flash attention (288 CTAs) + combine -> p_val [d, hw]
    flash_attn<<<dim3(24, NB, NSPLIT), 256, ATTN_SMEM_BYTES>>>(
        q_in, k_in, val, opart, lpart);
    attn_combine<<<dim3(24, NB), 256>>>(opart, lpart, pval);

    // 3) v2 = v + lrelu(conv3x3(p_val, w_out, pad=1))   [3xTF32]
    conv_mma<1><<<dim3(HWP / NTL, NB), 256, CONV_SMEM_BYTES>>>(
        pval, wtHi, wtLo, v_in, v2, 2);

    // 4) t1 = lrelu(conv3x3(v2, w_ff1, pad=2, dil=2))   [3xTF32]
    conv_mma<2><<<dim3(HWP / NTL, NB), 256, CONV_SMEM_BYTES>>>(
        v2, wtHi + WSZ, wtLo + WSZ, nullptr, t1, 1);

    // 5) out = v2 + lrelu(conv3x3(t1, w_ff2, pad=1))    [3xTF32]
    conv_mma<1><<<dim3(HWP / NTL, NB), 256, CONV_SMEM_BYTES>>>(
        t1, wtHi + 2 * WSZ, wtLo + 2 * WSZ, v2, out, 2);
}